// round 1
// baseline (speedup 1.0000x reference)
#include <cuda_runtime.h>
#include <math.h>

// Problem constants
#define S_LEN  4096
#define BATCH  4
#define NHEAD  16
#define DMODEL 1024
#define DKv    64          // head dim (v / output)
#define DDOT   128         // dpfp feature dim = 2*dk*NU
#define BHN    (BATCH*NHEAD)        // 64
#define MROWS  (S_LEN*BATCH)        // 16384
#define TOKENS (MROWS*NHEAD)        // 262144

typedef unsigned long long u64;

// ------------------------- scratch (static device memory) -------------------------
__device__ float g_qp  [(size_t)MROWS * DMODEL];   // x@Wq  [S,B,H,dk]
__device__ float g_kp  [(size_t)MROWS * DMODEL];   // x@Wk
__device__ float g_vv  [(size_t)MROWS * DMODEL];   // x@Wv
__device__ float g_beta[(size_t)MROWS * NHEAD];    // sigmoid(x@Wb) [S,B,H]
__device__ float g_phiq[(size_t)TOKENS * DDOT];    // dpfp(q) [S,B,H,128]
__device__ float g_phik[(size_t)TOKENS * DDOT];    // dpfp(k)
__device__ float g_kq  [(size_t)TOKENS];           // phi_k . phi_q per token
__device__ float g_y   [(size_t)MROWS * DMODEL];   // scan output [S,B,H,dk]

// ------------------------- f32x2 helpers -------------------------
__device__ __forceinline__ void fma2(u64 &d, u64 a, u64 b) {
    asm("fma.rn.f32x2 %0, %1, %2, %0;" : "+l"(d) : "l"(a), "l"(b));
}
__device__ __forceinline__ u64 add2(u64 a, u64 b) {
    u64 r; asm("add.rn.f32x2 %0, %1, %2;" : "=l"(r) : "l"(a), "l"(b)); return r;
}
__device__ __forceinline__ u64 pack2(float lo, float hi) {
    u64 r;
    asm("mov.b64 %0, {%1, %2};" : "=l"(r)
        : "r"(__float_as_uint(lo)), "r"(__float_as_uint(hi)));
    return r;
}
__device__ __forceinline__ float hadd2(u64 a) {
    unsigned lo, hi;
    asm("mov.b64 {%0, %1}, %2;" : "=r"(lo), "=r"(hi) : "l"(a));
    return __uint_as_float(lo) + __uint_as_float(hi);
}
__device__ __forceinline__ void load16(u64 d[8], const float* __restrict__ p) {
    union { float4 f; u64 u[2]; } t;
#pragma unroll
    for (int i = 0; i < 4; ++i) {
        t.f = *(const float4*)(p + i * 4);
        d[2*i]   = t.u[0];
        d[2*i+1] = t.u[1];
    }
}

// ------------------------- GEMM: C[M,N] = A[M,K] @ B[K,N] (+epilogue) -------------
// mode: 0 = none, 1 = sigmoid, 2 = +bias[n]
__global__ __launch_bounds__(256)
void gemm_kernel(const float* __restrict__ A, const float* __restrict__ B,
                 float* __restrict__ C, int M, int N, int K, int mode,
                 const float* __restrict__ bias)
{
    __shared__ float As[16][64];   // [k][m] (transposed for broadcast reads)
    __shared__ float Bs[16][64];   // [k][n]

    int tid = threadIdx.x;
    int tx = tid & 15;             // 0..15 -> 4 cols each
    int ty = tid >> 4;             // 0..15 -> 4 rows each
    int m0 = blockIdx.y * 64;
    int n0 = blockIdx.x * 64;

    int ar = tid >> 2;             // 0..63 A row within tile
    int ac = (tid & 3) * 4;        // k offset
    int br = tid >> 4;             // 0..15 B k-row
    int bc = (tid & 15) * 4;       // 0..60 col within tile

    float acc[4][4];
#pragma unroll
    for (int i = 0; i < 4; ++i)
#pragma unroll
        for (int j = 0; j < 4; ++j) acc[i][j] = 0.f;

    for (int k0 = 0; k0 < K; k0 += 16) {
        // A tile (M,K always multiples of tile here)
        float4 a4 = *(const float4*)(A + (size_t)(m0 + ar) * K + k0 + ac);
        As[ac + 0][ar] = a4.x;
        As[ac + 1][ar] = a4.y;
        As[ac + 2][ar] = a4.z;
        As[ac + 3][ar] = a4.w;
        // B tile with N guard
        int nb = n0 + bc;
        if (nb + 3 < N) {
            float4 b4 = *(const float4*)(B + (size_t)(k0 + br) * N + nb);
            Bs[br][bc + 0] = b4.x;
            Bs[br][bc + 1] = b4.y;
            Bs[br][bc + 2] = b4.z;
            Bs[br][bc + 3] = b4.w;
        } else {
#pragma unroll
            for (int e = 0; e < 4; ++e) {
                int n = nb + e;
                Bs[br][bc + e] = (n < N) ? B[(size_t)(k0 + br) * N + n] : 0.f;
            }
        }
        __syncthreads();
#pragma unroll
        for (int kk = 0; kk < 16; ++kk) {
            float4 a = *(const float4*)&As[kk][ty * 4];
            float4 b = *(const float4*)&Bs[kk][tx * 4];
            float av[4] = {a.x, a.y, a.z, a.w};
            float bv[4] = {b.x, b.y, b.z, b.w};
#pragma unroll
            for (int i = 0; i < 4; ++i)
#pragma unroll
                for (int j = 0; j < 4; ++j) acc[i][j] = fmaf(av[i], bv[j], acc[i][j]);
        }
        __syncthreads();
    }

#pragma unroll
    for (int i = 0; i < 4; ++i) {
        int m = m0 + ty * 4 + i;
        int nbase = n0 + tx * 4;
        float v[4];
#pragma unroll
        for (int j = 0; j < 4; ++j) {
            float t = acc[i][j];
            if (mode == 1) t = 1.f / (1.f + expf(-t));
            else if (mode == 2) t = t + bias[nbase + j < N ? nbase + j : 0];
            v[j] = t;
        }
        if (nbase + 3 < N) {
            *(float4*)(C + (size_t)m * N + nbase) = make_float4(v[0], v[1], v[2], v[3]);
        } else {
#pragma unroll
            for (int j = 0; j < 4; ++j)
                if (nbase + j < N) C[(size_t)m * N + nbase + j] = v[j];
        }
    }
}

// ------------------------- dpfp + kq precompute (one warp per token) --------------
__device__ __forceinline__ void dpfp_one(const float* __restrict__ src,
                                         float* __restrict__ dst,
                                         int lane, float outphi[4])
{
    // x2[i] = relu(k[i]) for i<64, relu(-k[i-64]) for i>=64.  Lane owns i in [4l,4l+3].
    int off = lane * 4 - ((lane >= 16) ? 64 : 0);
    float4 v = *(const float4*)(src + off);
    float sgn = (lane >= 16) ? -1.f : 1.f;
    float x0 = fmaxf(sgn * v.x, 0.f);
    float x1 = fmaxf(sgn * v.y, 0.f);
    float x2 = fmaxf(sgn * v.z, 0.f);
    float x3 = fmaxf(sgn * v.w, 0.f);
    // phi[i] = x2[i] * x2[(i-1) mod 128]
    float prev = __shfl_sync(0xffffffffu, x3, (lane + 31) & 31);
    float p0 = x0 * prev;
    float p1 = x1 * x0;
    float p2 = x2 * x1;
    float p3 = x3 * x2;
    float sum = (p0 + p1) + (p2 + p3);
#pragma unroll
    for (int o = 16; o > 0; o >>= 1) sum += __shfl_xor_sync(0xffffffffu, sum, o);
    float inv = 1.f / (sum + 1e-6f);
    p0 *= inv; p1 *= inv; p2 *= inv; p3 *= inv;
    *(float4*)(dst + lane * 4) = make_float4(p0, p1, p2, p3);
    outphi[0] = p0; outphi[1] = p1; outphi[2] = p2; outphi[3] = p3;
}

__global__ __launch_bounds__(256)
void dpfp_kq_kernel()
{
    int gw   = (blockIdx.x * 256 + threadIdx.x) >> 5;   // token index (s,b,h)
    int lane = threadIdx.x & 31;
    const float* qsrc = g_qp + (size_t)gw * DKv;
    const float* ksrc = g_kp + (size_t)gw * DKv;
    float pq[4], pk[4];
    dpfp_one(qsrc, g_phiq + (size_t)gw * DDOT, lane, pq);
    dpfp_one(ksrc, g_phik + (size_t)gw * DDOT, lane, pk);
    float s = pq[0] * pk[0] + pq[1] * pk[1] + pq[2] * pk[2] + pq[3] * pk[3];
#pragma unroll
    for (int o = 16; o > 0; o >>= 1) s += __shfl_xor_sync(0xffffffffu, s, o);
    if (lane == 0) g_kq[gw] = s;
}

// ------------------------- sequential fast-weight scan ----------------------------
// 4096 independent v-row chains. 8 lanes per chain (seg = lane&7), 4 chains per warp.
// Per lane: W row slice of 16 floats kept as 8 packed f32x2 registers.
__global__ __launch_bounds__(256)
void scan_kernel()
{
    int warp = (blockIdx.x * 256 + threadIdx.x) >> 5;   // 0..1023
    int lane = threadIdx.x & 31;
    int seg  = lane & 7;     // which 16-float slice of the 128-dim k axis
    int r    = lane >> 3;    // which of 4 rows in this warp
    int bh   = warp >> 4;    // 0..63 (b*H + h)
    int vg   = warp & 15;    // 16 row-groups of 4 per bh
    int row  = vg * 4 + r;   // 0..63 v-row

    const float* pk  = g_phik + (size_t)bh * DDOT + seg * 16;
    const float* pq  = g_phiq + (size_t)bh * DDOT + seg * 16;
    const float* pv  = g_vv   + (size_t)bh * DKv  + row;
    const float* pb  = g_beta + bh;
    const float* pqk = g_kq   + bh;
    float*       py  = g_y    + (size_t)bh * DKv  + row;

    u64 w2[8];
#pragma unroll
    for (int j = 0; j < 8; ++j) w2[j] = 0ull;

    // prime step 0
    u64 ck[8], cq[8];
    load16(ck, pk);
    load16(cq, pq);
    float cv  = __ldg(pv);
    float cb  = __ldg(pb);
    float ckq = __ldg(pqk);

#pragma unroll 2
    for (int s = 0; s < S_LEN; ++s) {
        // software-pipelined prefetch of next step (last iter reloads same addrs)
        if (s + 1 < S_LEN) {
            pk  += BHN * DDOT;
            pq  += BHN * DDOT;
            pv  += BHN * DKv;
            pb  += BHN;
            pqk += BHN;
        }
        u64 nk[8], nq[8];
        load16(nk, pk);
        load16(nq, pq);
        float nv  = __ldg(pv);
        float nb  = __ldg(pb);
        float nkq = __ldg(pqk);

        // two dots on W_old using packed FFMA2
        u64 ak0 = 0ull, ak1 = 0ull, aq0 = 0ull, aq1 = 0ull;
#pragma unroll
        for (int j = 0; j < 8; j += 2) {
            fma2(ak0, w2[j],     ck[j]);
            fma2(ak1, w2[j + 1], ck[j + 1]);
            fma2(aq0, w2[j],     cq[j]);
            fma2(aq1, w2[j + 1], cq[j + 1]);
        }
        float sk = hadd2(add2(ak0, ak1));
        float sq = hadd2(add2(aq0, aq1));
        // reduce across the 8 lanes of this chain
        sk += __shfl_xor_sync(0xffffffffu, sk, 1);
        sq += __shfl_xor_sync(0xffffffffu, sq, 1);
        sk += __shfl_xor_sync(0xffffffffu, sk, 2);
        sq += __shfl_xor_sync(0xffffffffu, sq, 2);
        sk += __shfl_xor_sync(0xffffffffu, sk, 4);
        sq += __shfl_xor_sync(0xffffffffu, sq, 4);

        float delta = cb * (cv - sk);
        float yv    = fmaf(delta, ckq, sq);   // y = W_new . q = W_old.q + delta*(k.q)
        if (seg == 0) *py = yv;
        py += BHN * DKv;

        // W += delta * k
        u64 d2 = pack2(delta, delta);
#pragma unroll
        for (int j = 0; j < 8; ++j) fma2(w2[j], d2, ck[j]);

        // rotate prefetched -> current
#pragma unroll
        for (int j = 0; j < 8; ++j) { ck[j] = nk[j]; cq[j] = nq[j]; }
        cv = nv; cb = nb; ckq = nkq;
    }
}

// ------------------------- launch -------------------------------------------------
extern "C" void kernel_launch(void* const* d_in, const int* in_sizes, int n_in,
                              void* d_out, int out_size)
{
    const float* x  = (const float*)d_in[0];
    const float* Wq = (const float*)d_in[1];
    const float* Wk = (const float*)d_in[2];
    const float* Wv = (const float*)d_in[3];
    const float* Wb = (const float*)d_in[4];
    const float* Wo = (const float*)d_in[5];
    const float* bo = (const float*)d_in[6];
    float* out = (float*)d_out;

    float *qp, *kp, *vv, *beta;
    cudaGetSymbolAddress((void**)&qp,   g_qp);
    cudaGetSymbolAddress((void**)&kp,   g_kp);
    cudaGetSymbolAddress((void**)&vv,   g_vv);
    cudaGetSymbolAddress((void**)&beta, g_beta);
    float* yb;
    cudaGetSymbolAddress((void**)&yb, g_y);

    dim3 blk(256);
    dim3 gP(DMODEL / 64, MROWS / 64);   // (16, 256)
    gemm_kernel<<<gP, blk>>>(x, Wq, qp, MROWS, DMODEL, DMODEL, 0, nullptr);
    gemm_kernel<<<gP, blk>>>(x, Wk, kp, MROWS, DMODEL, DMODEL, 0, nullptr);
    gemm_kernel<<<gP, blk>>>(x, Wv, vv, MROWS, DMODEL, DMODEL, 0, nullptr);
    dim3 gB(1, MROWS / 64);             // N = 16
    gemm_kernel<<<gB, blk>>>(x, Wb, beta, MROWS, NHEAD, DMODEL, 1, nullptr);

    dpfp_kq_kernel<<<TOKENS / 8, blk>>>();   // 8 warps per block

    scan_kernel<<<128, blk>>>();             // 1024 warps total

    gemm_kernel<<<gP, blk>>>(yb, Wo, out, MROWS, DMODEL, DMODEL, 2, bo);
}